// round 1
// baseline (speedup 1.0000x reference)
#include <cuda_runtime.h>

#define N_DIM 1024
#define M_DIM 2048
#define P_DIM 512
#define Q_DIM 128
#define KAPPA 0.99f
#define TOL   3e-6f
#define N_ITER 150

#define ADLD 260                     // padded dup-A smem row (floats), 4-aligned
#define ITER_SMEM_BYTES ((2*16*ADLD + 2*16*128) * 4)

// ---------------- device state ----------------
__device__ float g_Aproj[N_DIM * N_DIM];
__device__ float g_BU[N_DIM * M_DIM];
__device__ float g_X0buf[N_DIM * M_DIM];
__device__ float g_X1buf[N_DIM * M_DIM];
__device__ unsigned g_maxdiff;
__device__ int g_converged;
__device__ int g_cur;

union F4U { float4 f; unsigned long long u[2]; };

#define FMA2(d, a, b, c) \
    asm("fma.rn.f32x2 %0, %1, %2, %3;" : "=l"(d) : "l"(a), "l"(b), "l"(c))

// ---------------- init ----------------
__global__ void init_kernel() {
    g_maxdiff = 0u;
    g_converged = 0;
    g_cur = 0;
}

// ---------------- row-wise L-inf projection of A ----------------
__global__ __launch_bounds__(256) void project_kernel(const float* __restrict__ A) {
    __shared__ float warp_s[8];
    __shared__ float s_scale;
    int row = blockIdx.x;
    const float* ar = A + (long)row * N_DIM;
    float s = 0.f;
    for (int c = threadIdx.x; c < N_DIM; c += 256) s += fabsf(ar[c]);
#pragma unroll
    for (int o = 16; o; o >>= 1) s += __shfl_xor_sync(0xffffffffu, s, o);
    if ((threadIdx.x & 31) == 0) warp_s[threadIdx.x >> 5] = s;
    __syncthreads();
    if (threadIdx.x == 0) {
        float t = 0.f;
#pragma unroll
        for (int i = 0; i < 8; i++) t += warp_s[i];
        s_scale = fminf(1.f, KAPPA / fmaxf(t, 1e-12f));
    }
    __syncthreads();
    float sc = s_scale;
    float* outp = g_Aproj + (long)row * N_DIM;
    for (int c = threadIdx.x; c < N_DIM; c += 256) outp[c] = ar[c] * sc;
}

// ---------------- transpose X0 (m x n) -> g_X0buf (n x m) ----------------
__global__ void transpose_kernel(const float* __restrict__ in) {
    __shared__ float t[32][33];
    int i0 = blockIdx.x * 32;   // n index
    int j0 = blockIdx.y * 32;   // m index
    int x = threadIdx.x, y = threadIdx.y;
#pragma unroll
    for (int r = 0; r < 32; r += 8)
        t[y + r][x] = in[(long)(j0 + y + r) * N_DIM + i0 + x];
    __syncthreads();
#pragma unroll
    for (int r = 0; r < 32; r += 8)
        g_X0buf[(long)(i0 + y + r) * M_DIM + j0 + x] = t[x][y + r];
}

// ---------------- BU = B (n x p) @ U^T (p x m) ----------------
__global__ __launch_bounds__(256) void bu_kernel(const float* __restrict__ B,
                                                 const float* __restrict__ U) {
    __shared__ float Bs[16][132];
    __shared__ float Us[16][132];
    int i0 = blockIdx.y * 128, j0 = blockIdx.x * 128;
    int lk = threadIdx.x & 15, lb = threadIdx.x >> 4;
    int tx = threadIdx.x & 15, ty = threadIdx.x >> 4;
    float acc[8][8] = {};
    for (int kk = 0; kk < P_DIM; kk += 16) {
        __syncthreads();
#pragma unroll
        for (int r = 0; r < 8; r++) {
            Bs[lk][lb + 16 * r] = B[(long)(i0 + lb + 16 * r) * P_DIM + kk + lk];
            Us[lk][lb + 16 * r] = U[(long)(j0 + lb + 16 * r) * P_DIM + kk + lk];
        }
        __syncthreads();
#pragma unroll
        for (int k = 0; k < 16; k++) {
            float a[8], b[8];
#pragma unroll
            for (int i = 0; i < 8; i++) a[i] = Bs[k][ty * 8 + i];
#pragma unroll
            for (int j = 0; j < 8; j++) b[j] = Us[k][tx * 8 + j];
#pragma unroll
            for (int i = 0; i < 8; i++)
#pragma unroll
                for (int j = 0; j < 8; j++) acc[i][j] = fmaf(a[i], b[j], acc[i][j]);
        }
    }
#pragma unroll
    for (int i = 0; i < 8; i++) {
        long row = i0 + ty * 8 + i;
#pragma unroll
        for (int j = 0; j < 8; j++)
            g_BU[row * M_DIM + j0 + tx * 8 + j] = acc[i][j];
    }
}

// ---------------- Picard iteration: Xout = relu(Aproj @ Xin + BU) ----------------
__global__ __launch_bounds__(256, 1) void iter_kernel() {
    if (g_converged) return;
    int cur = g_cur;
    const float* __restrict__ Xin = cur ? g_X1buf : g_X0buf;
    float* __restrict__ Xout = cur ? g_X0buf : g_X1buf;

    extern __shared__ float sm[];
    float* AsD = sm;                 // [2][16][ADLD] duplicated A values
    float* Xs  = sm + 2 * 16 * ADLD; // [2][16][128]

    int i0 = blockIdx.y * 128;
    int j0 = blockIdx.x * 128;
    int tid = threadIdx.x;
    int lk = tid & 15, lb = tid >> 4;   // loader coords
    int tx = tid & 15, ty = tid >> 4;   // compute coords

    unsigned long long acc2[8][4];
#pragma unroll
    for (int i = 0; i < 8; i++)
#pragma unroll
        for (int j = 0; j < 4; j++) acc2[i][j] = 0ULL;

    float aReg[8];
    float4 xReg0, xReg1;

    // stage 0 global loads
#pragma unroll
    for (int r = 0; r < 8; r++)
        aReg[r] = g_Aproj[(long)(i0 + lb + 16 * r) * N_DIM + lk];
    {
        const float4* xp = (const float4*)(Xin + (long)lb * M_DIM + j0 + lk * 8);
        xReg0 = xp[0]; xReg1 = xp[1];
    }
    // stage 0 smem stores
#pragma unroll
    for (int r = 0; r < 8; r++) {
        float v = aReg[r];
        *(float2*)&AsD[(0 * 16 + lk) * ADLD + 2 * (lb + 16 * r)] = make_float2(v, v);
    }
    *(float4*)&Xs[(0 * 16 + lb) * 128 + lk * 8]     = xReg0;
    *(float4*)&Xs[(0 * 16 + lb) * 128 + lk * 8 + 4] = xReg1;
    __syncthreads();

    const int nst = N_DIM / 16;  // 64
    for (int s = 0; s < nst; s++) {
        int buf = s & 1;
        if (s + 1 < nst) {
            int kk = 16 * (s + 1);
#pragma unroll
            for (int r = 0; r < 8; r++)
                aReg[r] = g_Aproj[(long)(i0 + lb + 16 * r) * N_DIM + kk + lk];
            const float4* xp = (const float4*)(Xin + (long)(kk + lb) * M_DIM + j0 + lk * 8);
            xReg0 = xp[0]; xReg1 = xp[1];
        }
#pragma unroll
        for (int k = 0; k < 16; k++) {
            const float* abase = &AsD[(buf * 16 + k) * ADLD + 16 * ty];
            F4U av0, av1, av2, av3, bv0, bv1;
            av0.f = *(const float4*)(abase + 0);
            av1.f = *(const float4*)(abase + 4);
            av2.f = *(const float4*)(abase + 8);
            av3.f = *(const float4*)(abase + 12);
            const float* bbase = &Xs[(buf * 16 + k) * 128 + 8 * tx];
            bv0.f = *(const float4*)(bbase + 0);
            bv1.f = *(const float4*)(bbase + 4);
            unsigned long long a2[8] = {av0.u[0], av0.u[1], av1.u[0], av1.u[1],
                                        av2.u[0], av2.u[1], av3.u[0], av3.u[1]};
            unsigned long long b2[4] = {bv0.u[0], bv0.u[1], bv1.u[0], bv1.u[1]};
#pragma unroll
            for (int i = 0; i < 8; i++)
#pragma unroll
                for (int j = 0; j < 4; j++)
                    FMA2(acc2[i][j], a2[i], b2[j], acc2[i][j]);
        }
        if (s + 1 < nst) {
            int nbuf = buf ^ 1;
#pragma unroll
            for (int r = 0; r < 8; r++) {
                float v = aReg[r];
                *(float2*)&AsD[(nbuf * 16 + lk) * ADLD + 2 * (lb + 16 * r)] = make_float2(v, v);
            }
            *(float4*)&Xs[(nbuf * 16 + lb) * 128 + lk * 8]     = xReg0;
            *(float4*)&Xs[(nbuf * 16 + lb) * 128 + lk * 8 + 4] = xReg1;
        }
        __syncthreads();
    }

    // epilogue: add BU, relu, diff vs Xin, store, track max diff
    float maxd = 0.f;
#pragma unroll
    for (int ii = 0; ii < 8; ii++) {
        long off = (long)(i0 + ty * 8 + ii) * M_DIM + j0 + tx * 8;
        float4 bu0 = *(const float4*)(g_BU + off);
        float4 bu1 = *(const float4*)(g_BU + off + 4);
        float4 xo0 = *(const float4*)(Xin + off);
        float4 xo1 = *(const float4*)(Xin + off + 4);
        float rr[8];
#pragma unroll
        for (int jp = 0; jp < 4; jp++) {
            rr[2 * jp]     = __uint_as_float((unsigned)(acc2[ii][jp]));
            rr[2 * jp + 1] = __uint_as_float((unsigned)(acc2[ii][jp] >> 32));
        }
        float v0 = fmaxf(rr[0] + bu0.x, 0.f);
        float v1 = fmaxf(rr[1] + bu0.y, 0.f);
        float v2 = fmaxf(rr[2] + bu0.z, 0.f);
        float v3 = fmaxf(rr[3] + bu0.w, 0.f);
        float v4 = fmaxf(rr[4] + bu1.x, 0.f);
        float v5 = fmaxf(rr[5] + bu1.y, 0.f);
        float v6 = fmaxf(rr[6] + bu1.z, 0.f);
        float v7 = fmaxf(rr[7] + bu1.w, 0.f);
        maxd = fmaxf(maxd, fabsf(v0 - xo0.x));
        maxd = fmaxf(maxd, fabsf(v1 - xo0.y));
        maxd = fmaxf(maxd, fabsf(v2 - xo0.z));
        maxd = fmaxf(maxd, fabsf(v3 - xo0.w));
        maxd = fmaxf(maxd, fabsf(v4 - xo1.x));
        maxd = fmaxf(maxd, fabsf(v5 - xo1.y));
        maxd = fmaxf(maxd, fabsf(v6 - xo1.z));
        maxd = fmaxf(maxd, fabsf(v7 - xo1.w));
        *(float4*)(Xout + off)     = make_float4(v0, v1, v2, v3);
        *(float4*)(Xout + off + 4) = make_float4(v4, v5, v6, v7);
    }
#pragma unroll
    for (int o = 16; o; o >>= 1) maxd = fmaxf(maxd, __shfl_xor_sync(0xffffffffu, maxd, o));
    __shared__ float red[8];
    if ((tid & 31) == 0) red[tid >> 5] = maxd;
    __syncthreads();
    if (tid == 0) {
        float m = red[0];
#pragma unroll
        for (int i = 1; i < 8; i++) m = fmaxf(m, red[i]);
        atomicMax(&g_maxdiff, __float_as_uint(m));
    }
}

// ---------------- per-iteration convergence check ----------------
__global__ void check_kernel() {
    if (!g_converged) {
        float md = __uint_as_float(g_maxdiff);
        g_cur ^= 1;
        if (md <= TOL) g_converged = 1;
    }
    g_maxdiff = 0u;
}

// ---------------- output: out[j, y] = sum_k C[y,k] X[k,j] + sum_k D[y,k] U[j,k] ----------------
__global__ __launch_bounds__(256) void final_kernel(const float* __restrict__ Cm,
                                                    const float* __restrict__ Dm,
                                                    const float* __restrict__ U,
                                                    float* __restrict__ outp) {
    const float* __restrict__ X = g_cur ? g_X1buf : g_X0buf;
    __shared__ float As[16][132];
    __shared__ float Bs[16][132];
    int j0 = blockIdx.x * 128;
    int tid = threadIdx.x;
    int lk = tid & 15, lb = tid >> 4;
    int tx = tid & 15, ty = tid >> 4;
    float acc[8][8] = {};

    // part 1: C (q x n) @ X (n x m)
    for (int kk = 0; kk < N_DIM; kk += 16) {
        __syncthreads();
#pragma unroll
        for (int r = 0; r < 8; r++)
            As[lk][lb + 16 * r] = Cm[(long)(lb + 16 * r) * N_DIM + kk + lk];
        {
            const float4* xp = (const float4*)(X + (long)(kk + lb) * M_DIM + j0 + lk * 8);
            *(float4*)&Bs[lb][lk * 8]     = xp[0];
            *(float4*)&Bs[lb][lk * 8 + 4] = xp[1];
        }
        __syncthreads();
#pragma unroll
        for (int k = 0; k < 16; k++) {
            float a[8], b[8];
#pragma unroll
            for (int i = 0; i < 8; i++) a[i] = As[k][ty * 8 + i];
#pragma unroll
            for (int j = 0; j < 8; j++) b[j] = Bs[k][tx * 8 + j];
#pragma unroll
            for (int i = 0; i < 8; i++)
#pragma unroll
                for (int j = 0; j < 8; j++) acc[i][j] = fmaf(a[i], b[j], acc[i][j]);
        }
    }
    // part 2: D (q x p) @ U^T (p x m)
    for (int kk = 0; kk < P_DIM; kk += 16) {
        __syncthreads();
#pragma unroll
        for (int r = 0; r < 8; r++) {
            As[lk][lb + 16 * r] = Dm[(long)(lb + 16 * r) * P_DIM + kk + lk];
            Bs[lk][lb + 16 * r] = U[(long)(j0 + lb + 16 * r) * P_DIM + kk + lk];
        }
        __syncthreads();
#pragma unroll
        for (int k = 0; k < 16; k++) {
            float a[8], b[8];
#pragma unroll
            for (int i = 0; i < 8; i++) a[i] = As[k][ty * 8 + i];
#pragma unroll
            for (int j = 0; j < 8; j++) b[j] = Bs[k][tx * 8 + j];
#pragma unroll
            for (int i = 0; i < 8; i++)
#pragma unroll
                for (int j = 0; j < 8; j++) acc[i][j] = fmaf(a[i], b[j], acc[i][j]);
        }
    }
    // write transposed: out (m x q)
#pragma unroll
    for (int j = 0; j < 8; j++) {
        long col = j0 + tx * 8 + j;
#pragma unroll
        for (int i = 0; i < 8; i++)
            outp[col * Q_DIM + ty * 8 + i] = acc[i][j];
    }
}

// ---------------- launcher ----------------
extern "C" void kernel_launch(void* const* d_in, const int* in_sizes, int n_in,
                              void* d_out, int out_size) {
    (void)in_sizes; (void)n_in; (void)out_size;
    const float* U  = (const float*)d_in[0];
    const float* X0 = (const float*)d_in[1];
    const float* A  = (const float*)d_in[2];
    const float* B  = (const float*)d_in[3];
    const float* Cm = (const float*)d_in[4];
    const float* Dm = (const float*)d_in[5];
    float* outp = (float*)d_out;

    cudaFuncSetAttribute(iter_kernel, cudaFuncAttributeMaxDynamicSharedMemorySize,
                         ITER_SMEM_BYTES);

    init_kernel<<<1, 1>>>();
    project_kernel<<<N_DIM, 256>>>(A);
    transpose_kernel<<<dim3(N_DIM / 32, M_DIM / 32), dim3(32, 8)>>>(X0);
    bu_kernel<<<dim3(M_DIM / 128, N_DIM / 128), 256>>>(B, U);
    for (int it = 0; it < N_ITER; it++) {
        iter_kernel<<<dim3(M_DIM / 128, N_DIM / 128), 256, ITER_SMEM_BYTES>>>();
        check_kernel<<<1, 1>>>();
    }
    final_kernel<<<dim3(M_DIM / 128, 1), 256>>>(Cm, Dm, U, outp);
}

// round 2
// speedup vs baseline: 1.3437x; 1.3437x over previous
#include <cuda_runtime.h>

#define N_DIM 1024
#define M_DIM 2048
#define P_DIM 512
#define Q_DIM 128
#define KAPPA 0.99f
#define TOL   3e-6f
#define MAXIT 300
#define NBLK  128

#define ADLD 260                     // padded dup-A smem row (floats), 4-aligned
#define ITER_SMEM_BYTES ((2*16*ADLD + 2*16*128) * 4)

// ---------------- device state ----------------
__device__ float g_Aproj[N_DIM * N_DIM];
__device__ float g_BU[N_DIM * M_DIM];
__device__ float g_X0buf[N_DIM * M_DIM];
__device__ float g_X1buf[N_DIM * M_DIM];
__device__ unsigned g_md[MAXIT];
__device__ unsigned g_barcnt;
__device__ int g_cur;

union F4U { float4 f; unsigned long long u[2]; };

#define FMA2(d, a, b, c) \
    asm("fma.rn.f32x2 %0, %1, %2, %3;" : "=l"(d) : "l"(a), "l"(b), "l"(c))

// ---------------- init ----------------
__global__ void init_kernel() {
    int t = threadIdx.x;
    for (int i = t; i < MAXIT; i += 256) g_md[i] = 0u;
    if (t == 0) { g_barcnt = 0u; g_cur = 0; }
}

// ---------------- row-wise L-inf projection of A ----------------
__global__ __launch_bounds__(256) void project_kernel(const float* __restrict__ A) {
    __shared__ float warp_s[8];
    __shared__ float s_scale;
    int row = blockIdx.x;
    const float* ar = A + (long)row * N_DIM;
    float s = 0.f;
    for (int c = threadIdx.x; c < N_DIM; c += 256) s += fabsf(ar[c]);
#pragma unroll
    for (int o = 16; o; o >>= 1) s += __shfl_xor_sync(0xffffffffu, s, o);
    if ((threadIdx.x & 31) == 0) warp_s[threadIdx.x >> 5] = s;
    __syncthreads();
    if (threadIdx.x == 0) {
        float t = 0.f;
#pragma unroll
        for (int i = 0; i < 8; i++) t += warp_s[i];
        s_scale = fminf(1.f, KAPPA / fmaxf(t, 1e-12f));
    }
    __syncthreads();
    float sc = s_scale;
    float* outp = g_Aproj + (long)row * N_DIM;
    for (int c = threadIdx.x; c < N_DIM; c += 256) outp[c] = ar[c] * sc;
}

// ---------------- transpose X0 (m x n) -> g_X0buf (n x m) ----------------
__global__ void transpose_kernel(const float* __restrict__ in) {
    __shared__ float t[32][33];
    int i0 = blockIdx.x * 32;   // n index
    int j0 = blockIdx.y * 32;   // m index
    int x = threadIdx.x, y = threadIdx.y;
#pragma unroll
    for (int r = 0; r < 32; r += 8)
        t[y + r][x] = in[(long)(j0 + y + r) * N_DIM + i0 + x];
    __syncthreads();
#pragma unroll
    for (int r = 0; r < 32; r += 8)
        g_X0buf[(long)(i0 + y + r) * M_DIM + j0 + x] = t[x][y + r];
}

// ---------------- BU = B (n x p) @ U^T (p x m) ----------------
__global__ __launch_bounds__(256) void bu_kernel(const float* __restrict__ B,
                                                 const float* __restrict__ U) {
    __shared__ float Bs[16][132];
    __shared__ float Us[16][132];
    int i0 = blockIdx.y * 128, j0 = blockIdx.x * 128;
    int lk = threadIdx.x & 15, lb = threadIdx.x >> 4;
    int tx = threadIdx.x & 15, ty = threadIdx.x >> 4;
    float acc[8][8] = {};
    for (int kk = 0; kk < P_DIM; kk += 16) {
        __syncthreads();
#pragma unroll
        for (int r = 0; r < 8; r++) {
            Bs[lk][lb + 16 * r] = B[(long)(i0 + lb + 16 * r) * P_DIM + kk + lk];
            Us[lk][lb + 16 * r] = U[(long)(j0 + lb + 16 * r) * P_DIM + kk + lk];
        }
        __syncthreads();
#pragma unroll
        for (int k = 0; k < 16; k++) {
            float a[8], b[8];
#pragma unroll
            for (int i = 0; i < 8; i++) a[i] = Bs[k][ty * 8 + i];
#pragma unroll
            for (int j = 0; j < 8; j++) b[j] = Us[k][tx * 8 + j];
#pragma unroll
            for (int i = 0; i < 8; i++)
#pragma unroll
                for (int j = 0; j < 8; j++) acc[i][j] = fmaf(a[i], b[j], acc[i][j]);
        }
    }
#pragma unroll
    for (int i = 0; i < 8; i++) {
        long row = i0 + ty * 8 + i;
#pragma unroll
        for (int j = 0; j < 8; j++)
            g_BU[row * M_DIM + j0 + tx * 8 + j] = acc[i][j];
    }
}

// ---------------- persistent Picard loop: X <- relu(Aproj @ X + BU) until tol ----------------
__global__ __launch_bounds__(256, 1) void picard_kernel() {
    extern __shared__ float sm[];
    float* AsD = sm;                 // [2][16][ADLD] duplicated A values
    float* Xs  = sm + 2 * 16 * ADLD; // [2][16][128]

    int bid = blockIdx.x;
    int j0 = (bid & 15) * 128;       // m tile (16 tiles)
    int i0 = (bid >> 4) * 128;       // n tile (8 tiles)
    int tid = threadIdx.x;
    int lk = tid & 15, lb = tid >> 4;   // loader coords
    int tx = tid & 15, ty = tid >> 4;   // compute coords

    __shared__ float red[8];

    int it = 0;
    for (; it < MAXIT; it++) {
        const float* __restrict__ Xin = (it & 1) ? g_X1buf : g_X0buf;
        float* __restrict__ Xout = (it & 1) ? g_X0buf : g_X1buf;

        unsigned long long acc2[8][4];
#pragma unroll
        for (int i = 0; i < 8; i++)
#pragma unroll
            for (int j = 0; j < 4; j++) acc2[i][j] = 0ULL;

        float aReg[8];
        float4 xReg0, xReg1;

        // stage 0 global loads
#pragma unroll
        for (int r = 0; r < 8; r++)
            aReg[r] = g_Aproj[(long)(i0 + lb + 16 * r) * N_DIM + lk];
        {
            const float4* xp = (const float4*)(Xin + (long)lb * M_DIM + j0 + lk * 8);
            xReg0 = xp[0]; xReg1 = xp[1];
        }
        // stage 0 smem stores
#pragma unroll
        for (int r = 0; r < 8; r++) {
            float v = aReg[r];
            *(float2*)&AsD[(0 * 16 + lk) * ADLD + 2 * (lb + 16 * r)] = make_float2(v, v);
        }
        *(float4*)&Xs[(0 * 16 + lb) * 128 + lk * 8]     = xReg0;
        *(float4*)&Xs[(0 * 16 + lb) * 128 + lk * 8 + 4] = xReg1;
        __syncthreads();

        const int nst = N_DIM / 16;  // 64
        for (int s = 0; s < nst; s++) {
            int buf = s & 1;
            if (s + 1 < nst) {
                int kk = 16 * (s + 1);
#pragma unroll
                for (int r = 0; r < 8; r++)
                    aReg[r] = g_Aproj[(long)(i0 + lb + 16 * r) * N_DIM + kk + lk];
                const float4* xp = (const float4*)(Xin + (long)(kk + lb) * M_DIM + j0 + lk * 8);
                xReg0 = xp[0]; xReg1 = xp[1];
            }
#pragma unroll
            for (int k = 0; k < 16; k++) {
                const float* abase = &AsD[(buf * 16 + k) * ADLD + 16 * ty];
                F4U av0, av1, av2, av3, bv0, bv1;
                av0.f = *(const float4*)(abase + 0);
                av1.f = *(const float4*)(abase + 4);
                av2.f = *(const float4*)(abase + 8);
                av3.f = *(const float4*)(abase + 12);
                const float* bbase = &Xs[(buf * 16 + k) * 128 + 8 * tx];
                bv0.f = *(const float4*)(bbase + 0);
                bv1.f = *(const float4*)(bbase + 4);
                unsigned long long a2[8] = {av0.u[0], av0.u[1], av1.u[0], av1.u[1],
                                            av2.u[0], av2.u[1], av3.u[0], av3.u[1]};
                unsigned long long b2[4] = {bv0.u[0], bv0.u[1], bv1.u[0], bv1.u[1]};
#pragma unroll
                for (int i = 0; i < 8; i++)
#pragma unroll
                    for (int j = 0; j < 4; j++)
                        FMA2(acc2[i][j], a2[i], b2[j], acc2[i][j]);
            }
            if (s + 1 < nst) {
                int nbuf = buf ^ 1;
#pragma unroll
                for (int r = 0; r < 8; r++) {
                    float v = aReg[r];
                    *(float2*)&AsD[(nbuf * 16 + lk) * ADLD + 2 * (lb + 16 * r)] = make_float2(v, v);
                }
                *(float4*)&Xs[(nbuf * 16 + lb) * 128 + lk * 8]     = xReg0;
                *(float4*)&Xs[(nbuf * 16 + lb) * 128 + lk * 8 + 4] = xReg1;
            }
            __syncthreads();
        }

        // epilogue: add BU, relu, diff vs Xin, store, track max diff
        float maxd = 0.f;
#pragma unroll
        for (int ii = 0; ii < 8; ii++) {
            long off = (long)(i0 + ty * 8 + ii) * M_DIM + j0 + tx * 8;
            float4 bu0 = *(const float4*)(g_BU + off);
            float4 bu1 = *(const float4*)(g_BU + off + 4);
            float4 xo0 = *(const float4*)(Xin + off);
            float4 xo1 = *(const float4*)(Xin + off + 4);
            float rr[8];
#pragma unroll
            for (int jp = 0; jp < 4; jp++) {
                rr[2 * jp]     = __uint_as_float((unsigned)(acc2[ii][jp]));
                rr[2 * jp + 1] = __uint_as_float((unsigned)(acc2[ii][jp] >> 32));
            }
            float v0 = fmaxf(rr[0] + bu0.x, 0.f);
            float v1 = fmaxf(rr[1] + bu0.y, 0.f);
            float v2 = fmaxf(rr[2] + bu0.z, 0.f);
            float v3 = fmaxf(rr[3] + bu0.w, 0.f);
            float v4 = fmaxf(rr[4] + bu1.x, 0.f);
            float v5 = fmaxf(rr[5] + bu1.y, 0.f);
            float v6 = fmaxf(rr[6] + bu1.z, 0.f);
            float v7 = fmaxf(rr[7] + bu1.w, 0.f);
            maxd = fmaxf(maxd, fabsf(v0 - xo0.x));
            maxd = fmaxf(maxd, fabsf(v1 - xo0.y));
            maxd = fmaxf(maxd, fabsf(v2 - xo0.z));
            maxd = fmaxf(maxd, fabsf(v3 - xo0.w));
            maxd = fmaxf(maxd, fabsf(v4 - xo1.x));
            maxd = fmaxf(maxd, fabsf(v5 - xo1.y));
            maxd = fmaxf(maxd, fabsf(v6 - xo1.z));
            maxd = fmaxf(maxd, fabsf(v7 - xo1.w));
            *(float4*)(Xout + off)     = make_float4(v0, v1, v2, v3);
            *(float4*)(Xout + off + 4) = make_float4(v4, v5, v6, v7);
        }
#pragma unroll
        for (int o = 16; o; o >>= 1) maxd = fmaxf(maxd, __shfl_xor_sync(0xffffffffu, maxd, o));
        if ((tid & 31) == 0) red[tid >> 5] = maxd;
        __syncthreads();
        if (tid == 0) {
            float m = red[0];
#pragma unroll
            for (int i = 1; i < 8; i++) m = fmaxf(m, red[i]);
            atomicMax(&g_md[it], __float_as_uint(m));
        }

        // ---- software grid barrier (all 128 blocks co-resident: 128 <= 148 SMs) ----
        __syncthreads();
        if (tid == 0) {
            __threadfence();
            atomicAdd(&g_barcnt, 1u);
            unsigned target = (unsigned)(it + 1) * NBLK;
            while (atomicAdd(&g_barcnt, 0u) < target) {}
            __threadfence();
        }
        __syncthreads();

        // uniform convergence decision across all blocks
        float md = __uint_as_float(g_md[it]);
        if (md <= TOL) { it++; break; }
    }

    if (bid == 0 && tid == 0) g_cur = it & 1;   // buffer holding final X
}

// ---------------- output: out[j, y] = sum_k C[y,k] X[k,j] + sum_k D[y,k] U[j,k] ----------------
__global__ __launch_bounds__(256) void final_kernel(const float* __restrict__ Cm,
                                                    const float* __restrict__ Dm,
                                                    const float* __restrict__ U,
                                                    float* __restrict__ outp) {
    const float* __restrict__ X = g_cur ? g_X1buf : g_X0buf;
    __shared__ float As[16][132];
    __shared__ float Bs[16][132];
    int j0 = blockIdx.x * 128;
    int tid = threadIdx.x;
    int lk = tid & 15, lb = tid >> 4;
    int tx = tid & 15, ty = tid >> 4;
    float acc[8][8] = {};

    // part 1: C (q x n) @ X (n x m)
    for (int kk = 0; kk < N_DIM; kk += 16) {
        __syncthreads();
#pragma unroll
        for (int r = 0; r < 8; r++)
            As[lk][lb + 16 * r] = Cm[(long)(lb + 16 * r) * N_DIM + kk + lk];
        {
            const float4* xp = (const float4*)(X + (long)(kk + lb) * M_DIM + j0 + lk * 8);
            *(float4*)&Bs[lb][lk * 8]     = xp[0];
            *(float4*)&Bs[lb][lk * 8 + 4] = xp[1];
        }
        __syncthreads();
#pragma unroll
        for (int k = 0; k < 16; k++) {
            float a[8], b[8];
#pragma unroll
            for (int i = 0; i < 8; i++) a[i] = As[k][ty * 8 + i];
#pragma unroll
            for (int j = 0; j < 8; j++) b[j] = Bs[k][tx * 8 + j];
#pragma unroll
            for (int i = 0; i < 8; i++)
#pragma unroll
                for (int j = 0; j < 8; j++) acc[i][j] = fmaf(a[i], b[j], acc[i][j]);
        }
    }
    // part 2: D (q x p) @ U^T (p x m)
    for (int kk = 0; kk < P_DIM; kk += 16) {
        __syncthreads();
#pragma unroll
        for (int r = 0; r < 8; r++) {
            As[lk][lb + 16 * r] = Dm[(long)(lb + 16 * r) * P_DIM + kk + lk];
            Bs[lk][lb + 16 * r] = U[(long)(j0 + lb + 16 * r) * P_DIM + kk + lk];
        }
        __syncthreads();
#pragma unroll
        for (int k = 0; k < 16; k++) {
            float a[8], b[8];
#pragma unroll
            for (int i = 0; i < 8; i++) a[i] = As[k][ty * 8 + i];
#pragma unroll
            for (int j = 0; j < 8; j++) b[j] = Bs[k][tx * 8 + j];
#pragma unroll
            for (int i = 0; i < 8; i++)
#pragma unroll
                for (int j = 0; j < 8; j++) acc[i][j] = fmaf(a[i], b[j], acc[i][j]);
        }
    }
    // write transposed: out (m x q)
#pragma unroll
    for (int j = 0; j < 8; j++) {
        long col = j0 + tx * 8 + j;
#pragma unroll
        for (int i = 0; i < 8; i++)
            outp[col * Q_DIM + ty * 8 + i] = acc[i][j];
    }
}

// ---------------- launcher ----------------
extern "C" void kernel_launch(void* const* d_in, const int* in_sizes, int n_in,
                              void* d_out, int out_size) {
    (void)in_sizes; (void)n_in; (void)out_size;
    const float* U  = (const float*)d_in[0];
    const float* X0 = (const float*)d_in[1];
    const float* A  = (const float*)d_in[2];
    const float* B  = (const float*)d_in[3];
    const float* Cm = (const float*)d_in[4];
    const float* Dm = (const float*)d_in[5];
    float* outp = (float*)d_out;

    cudaFuncSetAttribute(picard_kernel, cudaFuncAttributeMaxDynamicSharedMemorySize,
                         ITER_SMEM_BYTES);

    init_kernel<<<1, 256>>>();
    project_kernel<<<N_DIM, 256>>>(A);
    transpose_kernel<<<dim3(N_DIM / 32, M_DIM / 32), dim3(32, 8)>>>(X0);
    bu_kernel<<<dim3(M_DIM / 128, N_DIM / 128), 256>>>(B, U);
    picard_kernel<<<NBLK, 256, ITER_SMEM_BYTES>>>();
    final_kernel<<<dim3(M_DIM / 128, 1), 256>>>(Cm, Dm, U, outp);
}

// round 3
// speedup vs baseline: 1.3453x; 1.0012x over previous
#include <cuda_runtime.h>

#define N_DIM 1024
#define M_DIM 2048
#define P_DIM 512
#define Q_DIM 128
#define KAPPA 0.99f
#define TOL   3e-6f
#define MAXIT 300
#define NBLK  128

#define ADLD 260                     // padded dup-A smem row (floats), 4-aligned
#define ITER_SMEM_BYTES ((2*16*ADLD + 2*16*128) * 4)

// ---------------- device state ----------------
__device__ float g_Aproj[N_DIM * N_DIM];
__device__ float g_BU[N_DIM * M_DIM];
__device__ float g_X0buf[N_DIM * M_DIM];
__device__ float g_X1buf[N_DIM * M_DIM];
__device__ unsigned g_md[MAXIT];
__device__ unsigned g_barcnt;
__device__ int g_cur;

union F4U { float4 f; unsigned long long u[2]; };

#define FMA2(d, a, b, c) \
    asm("fma.rn.f32x2 %0, %1, %2, %3;" : "=l"(d) : "l"(a), "l"(b), "l"(c))

// ---------------- init ----------------
__global__ void init_kernel() {
    int t = threadIdx.x;
    for (int i = t; i < MAXIT; i += 256) g_md[i] = 0u;
    if (t == 0) { g_barcnt = 0u; g_cur = 0; }
}

// ---------------- row-wise L-inf projection of A ----------------
__global__ __launch_bounds__(256) void project_kernel(const float* __restrict__ A) {
    __shared__ float warp_s[8];
    __shared__ float s_scale;
    int row = blockIdx.x;
    const float* ar = A + (long)row * N_DIM;
    float s = 0.f;
    for (int c = threadIdx.x; c < N_DIM; c += 256) s += fabsf(ar[c]);
#pragma unroll
    for (int o = 16; o; o >>= 1) s += __shfl_xor_sync(0xffffffffu, s, o);
    if ((threadIdx.x & 31) == 0) warp_s[threadIdx.x >> 5] = s;
    __syncthreads();
    if (threadIdx.x == 0) {
        float t = 0.f;
#pragma unroll
        for (int i = 0; i < 8; i++) t += warp_s[i];
        s_scale = fminf(1.f, KAPPA / fmaxf(t, 1e-12f));
    }
    __syncthreads();
    float sc = s_scale;
    float* outp = g_Aproj + (long)row * N_DIM;
    for (int c = threadIdx.x; c < N_DIM; c += 256) outp[c] = ar[c] * sc;
}

// ---------------- transpose X0 (m x n) -> g_X0buf (n x m) ----------------
__global__ void transpose_kernel(const float* __restrict__ in) {
    __shared__ float t[32][33];
    int i0 = blockIdx.x * 32;   // n index
    int j0 = blockIdx.y * 32;   // m index
    int x = threadIdx.x, y = threadIdx.y;
#pragma unroll
    for (int r = 0; r < 32; r += 8)
        t[y + r][x] = in[(long)(j0 + y + r) * N_DIM + i0 + x];
    __syncthreads();
#pragma unroll
    for (int r = 0; r < 32; r += 8)
        g_X0buf[(long)(i0 + y + r) * M_DIM + j0 + x] = t[x][y + r];
}

// ---------------- BU = B (n x p) @ U^T (p x m) ----------------
__global__ __launch_bounds__(256) void bu_kernel(const float* __restrict__ B,
                                                 const float* __restrict__ U) {
    __shared__ float Bs[16][132];
    __shared__ float Us[16][132];
    int i0 = blockIdx.y * 128, j0 = blockIdx.x * 128;
    int lk = threadIdx.x & 15, lb = threadIdx.x >> 4;
    int tx = threadIdx.x & 15, ty = threadIdx.x >> 4;
    float acc[8][8] = {};
    for (int kk = 0; kk < P_DIM; kk += 16) {
        __syncthreads();
#pragma unroll
        for (int r = 0; r < 8; r++) {
            Bs[lk][lb + 16 * r] = B[(long)(i0 + lb + 16 * r) * P_DIM + kk + lk];
            Us[lk][lb + 16 * r] = U[(long)(j0 + lb + 16 * r) * P_DIM + kk + lk];
        }
        __syncthreads();
#pragma unroll
        for (int k = 0; k < 16; k++) {
            float a[8], b[8];
#pragma unroll
            for (int i = 0; i < 8; i++) a[i] = Bs[k][ty * 8 + i];
#pragma unroll
            for (int j = 0; j < 8; j++) b[j] = Us[k][tx * 8 + j];
#pragma unroll
            for (int i = 0; i < 8; i++)
#pragma unroll
                for (int j = 0; j < 8; j++) acc[i][j] = fmaf(a[i], b[j], acc[i][j]);
        }
    }
#pragma unroll
    for (int i = 0; i < 8; i++) {
        long row = i0 + ty * 8 + i;
#pragma unroll
        for (int j = 0; j < 8; j++)
            g_BU[row * M_DIM + j0 + tx * 8 + j] = acc[i][j];
    }
}

// ---------------- persistent Picard loop: X <- relu(Aproj @ X + BU) until tol ----------------
__global__ __launch_bounds__(256, 1) void picard_kernel() {
    extern __shared__ float sm[];
    float* AsD = sm;                 // [2][16][ADLD] duplicated A values
    float* Xs  = sm + 2 * 16 * ADLD; // [2][16][128]

    int bid = blockIdx.x;
    int j0 = (bid & 15) * 128;       // m tile (16 tiles)
    int i0 = (bid >> 4) * 128;       // n tile (8 tiles)
    int tid = threadIdx.x;
    int lk = tid & 15, lb = tid >> 4;   // loader coords
    int tx = tid & 15, ty = tid >> 4;   // compute coords

    __shared__ float red[8];

    int it = 0;
    for (; it < MAXIT; it++) {
        const float* __restrict__ Xin = (it & 1) ? g_X1buf : g_X0buf;
        float* __restrict__ Xout = (it & 1) ? g_X0buf : g_X1buf;

        unsigned long long acc2[8][4];
#pragma unroll
        for (int i = 0; i < 8; i++)
#pragma unroll
            for (int j = 0; j < 4; j++) acc2[i][j] = 0ULL;

        float aReg[8];
        float4 xReg0, xReg1;

        // stage 0 global loads
#pragma unroll
        for (int r = 0; r < 8; r++)
            aReg[r] = g_Aproj[(long)(i0 + lb + 16 * r) * N_DIM + lk];
        {
            const float4* xp = (const float4*)(Xin + (long)lb * M_DIM + j0 + lk * 8);
            xReg0 = xp[0]; xReg1 = xp[1];
        }
        // stage 0 smem stores
#pragma unroll
        for (int r = 0; r < 8; r++) {
            float v = aReg[r];
            *(float2*)&AsD[(0 * 16 + lk) * ADLD + 2 * (lb + 16 * r)] = make_float2(v, v);
        }
        *(float4*)&Xs[(0 * 16 + lb) * 128 + lk * 8]     = xReg0;
        *(float4*)&Xs[(0 * 16 + lb) * 128 + lk * 8 + 4] = xReg1;
        __syncthreads();

        const int nst = N_DIM / 16;  // 64
        for (int s = 0; s < nst; s++) {
            int buf = s & 1;
            if (s + 1 < nst) {
                int kk = 16 * (s + 1);
#pragma unroll
                for (int r = 0; r < 8; r++)
                    aReg[r] = g_Aproj[(long)(i0 + lb + 16 * r) * N_DIM + kk + lk];
                const float4* xp = (const float4*)(Xin + (long)(kk + lb) * M_DIM + j0 + lk * 8);
                xReg0 = xp[0]; xReg1 = xp[1];
            }
#pragma unroll
            for (int k = 0; k < 16; k++) {
                const float* abase = &AsD[(buf * 16 + k) * ADLD + 16 * ty];
                F4U av0, av1, av2, av3, bv0, bv1;
                av0.f = *(const float4*)(abase + 0);
                av1.f = *(const float4*)(abase + 4);
                av2.f = *(const float4*)(abase + 8);
                av3.f = *(const float4*)(abase + 12);
                const float* bbase = &Xs[(buf * 16 + k) * 128 + 8 * tx];
                bv0.f = *(const float4*)(bbase + 0);
                bv1.f = *(const float4*)(bbase + 4);
                unsigned long long a2[8] = {av0.u[0], av0.u[1], av1.u[0], av1.u[1],
                                            av2.u[0], av2.u[1], av3.u[0], av3.u[1]};
                unsigned long long b2[4] = {bv0.u[0], bv0.u[1], bv1.u[0], bv1.u[1]};
#pragma unroll
                for (int i = 0; i < 8; i++)
#pragma unroll
                    for (int j = 0; j < 4; j++)
                        FMA2(acc2[i][j], a2[i], b2[j], acc2[i][j]);
            }
            if (s + 1 < nst) {
                int nbuf = buf ^ 1;
#pragma unroll
                for (int r = 0; r < 8; r++) {
                    float v = aReg[r];
                    *(float2*)&AsD[(nbuf * 16 + lk) * ADLD + 2 * (lb + 16 * r)] = make_float2(v, v);
                }
                *(float4*)&Xs[(nbuf * 16 + lb) * 128 + lk * 8]     = xReg0;
                *(float4*)&Xs[(nbuf * 16 + lb) * 128 + lk * 8 + 4] = xReg1;
            }
            __syncthreads();
        }

        // epilogue: add BU, relu, diff vs Xin, store, track max diff
        float maxd = 0.f;
#pragma unroll
        for (int ii = 0; ii < 8; ii++) {
            long off = (long)(i0 + ty * 8 + ii) * M_DIM + j0 + tx * 8;
            float4 bu0 = *(const float4*)(g_BU + off);
            float4 bu1 = *(const float4*)(g_BU + off + 4);
            float4 xo0 = *(const float4*)(Xin + off);
            float4 xo1 = *(const float4*)(Xin + off + 4);
            float rr[8];
#pragma unroll
            for (int jp = 0; jp < 4; jp++) {
                rr[2 * jp]     = __uint_as_float((unsigned)(acc2[ii][jp]));
                rr[2 * jp + 1] = __uint_as_float((unsigned)(acc2[ii][jp] >> 32));
            }
            float v0 = fmaxf(rr[0] + bu0.x, 0.f);
            float v1 = fmaxf(rr[1] + bu0.y, 0.f);
            float v2 = fmaxf(rr[2] + bu0.z, 0.f);
            float v3 = fmaxf(rr[3] + bu0.w, 0.f);
            float v4 = fmaxf(rr[4] + bu1.x, 0.f);
            float v5 = fmaxf(rr[5] + bu1.y, 0.f);
            float v6 = fmaxf(rr[6] + bu1.z, 0.f);
            float v7 = fmaxf(rr[7] + bu1.w, 0.f);
            maxd = fmaxf(maxd, fabsf(v0 - xo0.x));
            maxd = fmaxf(maxd, fabsf(v1 - xo0.y));
            maxd = fmaxf(maxd, fabsf(v2 - xo0.z));
            maxd = fmaxf(maxd, fabsf(v3 - xo0.w));
            maxd = fmaxf(maxd, fabsf(v4 - xo1.x));
            maxd = fmaxf(maxd, fabsf(v5 - xo1.y));
            maxd = fmaxf(maxd, fabsf(v6 - xo1.z));
            maxd = fmaxf(maxd, fabsf(v7 - xo1.w));
            *(float4*)(Xout + off)     = make_float4(v0, v1, v2, v3);
            *(float4*)(Xout + off + 4) = make_float4(v4, v5, v6, v7);
        }
#pragma unroll
        for (int o = 16; o; o >>= 1) maxd = fmaxf(maxd, __shfl_xor_sync(0xffffffffu, maxd, o));
        if ((tid & 31) == 0) red[tid >> 5] = maxd;
        __syncthreads();
        if (tid == 0) {
            float m = red[0];
#pragma unroll
            for (int i = 1; i < 8; i++) m = fmaxf(m, red[i]);
            atomicMax(&g_md[it], __float_as_uint(m));
        }

        // ---- software grid barrier (all 128 blocks co-resident: 128 <= 148 SMs) ----
        __syncthreads();
        if (tid == 0) {
            __threadfence();
            atomicAdd(&g_barcnt, 1u);
            unsigned target = (unsigned)(it + 1) * NBLK;
            while (atomicAdd(&g_barcnt, 0u) < target) {}
            __threadfence();
        }
        __syncthreads();

        // uniform convergence decision across all blocks
        float md = __uint_as_float(g_md[it]);
        if (md <= TOL) { it++; break; }
    }

    if (bid == 0 && tid == 0) g_cur = it & 1;   // buffer holding final X
}

// ---------------- output: out[j, y] = sum_k C[y,k] X[k,j] + sum_k D[y,k] U[j,k] ----------------
__global__ __launch_bounds__(256) void final_kernel(const float* __restrict__ Cm,
                                                    const float* __restrict__ Dm,
                                                    const float* __restrict__ U,
                                                    float* __restrict__ outp) {
    const float* __restrict__ X = g_cur ? g_X1buf : g_X0buf;
    __shared__ float As[16][132];
    __shared__ float Bs[16][132];
    int j0 = blockIdx.x * 128;
    int tid = threadIdx.x;
    int lk = tid & 15, lb = tid >> 4;
    int tx = tid & 15, ty = tid >> 4;
    float acc[8][8] = {};

    // part 1: C (q x n) @ X (n x m)
    for (int kk = 0; kk < N_DIM; kk += 16) {
        __syncthreads();
#pragma unroll
        for (int r = 0; r < 8; r++)
            As[lk][lb + 16 * r] = Cm[(long)(lb + 16 * r) * N_DIM + kk + lk];
        {
            const float4* xp = (const float4*)(X + (long)(kk + lb) * M_DIM + j0 + lk * 8);
            *(float4*)&Bs[lb][lk * 8]     = xp[0];
            *(float4*)&Bs[lb][lk * 8 + 4] = xp[1];
        }
        __syncthreads();
#pragma unroll
        for (int k = 0; k < 16; k++) {
            float a[8], b[8];
#pragma unroll
            for (int i = 0; i < 8; i++) a[i] = As[k][ty * 8 + i];
#pragma unroll
            for (int j = 0; j < 8; j++) b[j] = Bs[k][tx * 8 + j];
#pragma unroll
            for (int i = 0; i < 8; i++)
#pragma unroll
                for (int j = 0; j < 8; j++) acc[i][j] = fmaf(a[i], b[j], acc[i][j]);
        }
    }
    // part 2: D (q x p) @ U^T (p x m)
    for (int kk = 0; kk < P_DIM; kk += 16) {
        __syncthreads();
#pragma unroll
        for (int r = 0; r < 8; r++) {
            As[lk][lb + 16 * r] = Dm[(long)(lb + 16 * r) * P_DIM + kk + lk];
            Bs[lk][lb + 16 * r] = U[(long)(j0 + lb + 16 * r) * P_DIM + kk + lk];
        }
        __syncthreads();
#pragma unroll
        for (int k = 0; k < 16; k++) {
            float a[8], b[8];
#pragma unroll
            for (int i = 0; i < 8; i++) a[i] = As[k][ty * 8 + i];
#pragma unroll
            for (int j = 0; j < 8; j++) b[j] = Bs[k][tx * 8 + j];
#pragma unroll
            for (int i = 0; i < 8; i++)
#pragma unroll
                for (int j = 0; j < 8; j++) acc[i][j] = fmaf(a[i], b[j], acc[i][j]);
        }
    }
    // write transposed: out (m x q)
#pragma unroll
    for (int j = 0; j < 8; j++) {
        long col = j0 + tx * 8 + j;
#pragma unroll
        for (int i = 0; i < 8; i++)
            outp[col * Q_DIM + ty * 8 + i] = acc[i][j];
    }
}

// ---------------- launcher ----------------
extern "C" void kernel_launch(void* const* d_in, const int* in_sizes, int n_in,
                              void* d_out, int out_size) {
    (void)in_sizes; (void)n_in; (void)out_size;
    const float* U  = (const float*)d_in[0];
    const float* X0 = (const float*)d_in[1];
    const float* A  = (const float*)d_in[2];
    const float* B  = (const float*)d_in[3];
    const float* Cm = (const float*)d_in[4];
    const float* Dm = (const float*)d_in[5];
    float* outp = (float*)d_out;

    cudaFuncSetAttribute(picard_kernel, cudaFuncAttributeMaxDynamicSharedMemorySize,
                         ITER_SMEM_BYTES);

    init_kernel<<<1, 256>>>();
    project_kernel<<<N_DIM, 256>>>(A);
    transpose_kernel<<<dim3(N_DIM / 32, M_DIM / 32), dim3(32, 8)>>>(X0);
    bu_kernel<<<dim3(M_DIM / 128, N_DIM / 128), 256>>>(B, U);
    picard_kernel<<<NBLK, 256, ITER_SMEM_BYTES>>>();
    final_kernel<<<dim3(M_DIM / 128, 1), 256>>>(Cm, Dm, U, outp);
}

// round 5
// speedup vs baseline: 1.8672x; 1.3879x over previous
#include <cuda_runtime.h>
#include <cstdint>

#define N_DIM 1024
#define M_DIM 2048
#define P_DIM 512
#define Q_DIM 128
#define KAPPA 0.99f
#define TOL   3e-6f
#define MAXIT 300
#define NBLK  128

#define KC   16
#define LDA  20   // padded smem row (floats); stride-20 bank walk is conflict-free

// ---------------- device state ----------------
__device__ float g_Aproj[(size_t)N_DIM * N_DIM];
__device__ float g_BU[(size_t)M_DIM * N_DIM];     // m-major
__device__ float g_X0buf[(size_t)M_DIM * N_DIM];  // m-major
__device__ float g_X1buf[(size_t)M_DIM * N_DIM];
__device__ float g_part[4][(size_t)M_DIM * Q_DIM];
__device__ unsigned g_md[MAXIT];
__device__ unsigned g_barcnt;
__device__ int g_cur;

// ---------------- helpers ----------------
__device__ __forceinline__ uint32_t f2tf(float x) {
    uint32_t r;
    asm("cvt.rna.tf32.f32 %0, %1;" : "=r"(r) : "f"(x));
    return r;
}
__device__ __forceinline__ void mma8(float* d, const uint32_t* a, const uint32_t* b) {
    asm volatile(
        "mma.sync.aligned.m16n8k8.row.col.f32.tf32.tf32.f32 "
        "{%0,%1,%2,%3},{%4,%5,%6,%7},{%8,%9},{%0,%1,%2,%3};"
        : "+f"(d[0]), "+f"(d[1]), "+f"(d[2]), "+f"(d[3])
        : "r"(a[0]), "r"(a[1]), "r"(a[2]), "r"(a[3]), "r"(b[0]), "r"(b[1]));
}

// ---------------- init ----------------
__global__ void init_kernel() {
    int t = threadIdx.x;
    for (int i = t; i < MAXIT; i += 256) g_md[i] = 0u;
    if (t == 0) { g_barcnt = 0u; g_cur = 0; }
}

// ---------------- row-wise L-inf projection of A ----------------
__global__ __launch_bounds__(256) void project_kernel(const float* __restrict__ A) {
    __shared__ float warp_s[8];
    __shared__ float s_scale;
    int row = blockIdx.x;
    const float* ar = A + (size_t)row * N_DIM;
    float s = 0.f;
    for (int c = threadIdx.x; c < N_DIM; c += 256) s += fabsf(ar[c]);
#pragma unroll
    for (int o = 16; o; o >>= 1) s += __shfl_xor_sync(0xffffffffu, s, o);
    if ((threadIdx.x & 31) == 0) warp_s[threadIdx.x >> 5] = s;
    __syncthreads();
    if (threadIdx.x == 0) {
        float t = 0.f;
#pragma unroll
        for (int i = 0; i < 8; i++) t += warp_s[i];
        s_scale = fminf(1.f, KAPPA / fmaxf(t, 1e-12f));
    }
    __syncthreads();
    float sc = s_scale;
    float* outp = g_Aproj + (size_t)row * N_DIM;
    for (int c = threadIdx.x; c < N_DIM; c += 256) outp[c] = ar[c] * sc;
}

// ---------------- X0 (m,n) row-major == m-major: straight copy ----------------
__global__ void copyx0_kernel(const float* __restrict__ in) {
    size_t idx = (size_t)blockIdx.x * 256 + threadIdx.x;
    const float4* src = (const float4*)in;
    float4* dst = (float4*)g_X0buf;
    size_t tot = (size_t)M_DIM * N_DIM / 4;
    for (size_t i = idx; i < tot; i += (size_t)gridDim.x * 256) dst[i] = src[i];
}

// ---------------- BU[j][i] = sum_p B[i,p] U[j,p]  (m-major out) ----------------
__global__ __launch_bounds__(256) void bu_kernel(const float* __restrict__ B,
                                                 const float* __restrict__ U) {
    __shared__ float Bs[16][68];
    __shared__ float Us[16][132];
    int i0 = blockIdx.y * 64, j0 = blockIdx.x * 128;
    int lk = threadIdx.x & 15, lb = threadIdx.x >> 4;
    int tx = threadIdx.x & 15, ty = threadIdx.x >> 4;
    float acc[4][8] = {};
    for (int kk = 0; kk < P_DIM; kk += 16) {
        __syncthreads();
#pragma unroll
        for (int r = 0; r < 4; r++)
            Bs[lk][lb + 16 * r] = B[(size_t)(i0 + lb + 16 * r) * P_DIM + kk + lk];
#pragma unroll
        for (int r = 0; r < 8; r++)
            Us[lk][lb + 16 * r] = U[(size_t)(j0 + lb + 16 * r) * P_DIM + kk + lk];
        __syncthreads();
#pragma unroll
        for (int k = 0; k < 16; k++) {
            float a[4], b[8];
#pragma unroll
            for (int i = 0; i < 4; i++) a[i] = Bs[k][ty * 4 + i];
#pragma unroll
            for (int j = 0; j < 8; j++) b[j] = Us[k][tx * 8 + j];
#pragma unroll
            for (int i = 0; i < 4; i++)
#pragma unroll
                for (int j = 0; j < 8; j++) acc[i][j] = fmaf(a[i], b[j], acc[i][j]);
        }
    }
#pragma unroll
    for (int j = 0; j < 8; j++) {
        size_t off = (size_t)(j0 + tx * 8 + j) * N_DIM + i0 + ty * 4;
        *(float4*)(g_BU + off) = make_float4(acc[0][j], acc[1][j], acc[2][j], acc[3][j]);
    }
}

// ---------------- persistent TF32-MMA Picard loop ----------------
__global__ __launch_bounds__(256, 1) void picard_kernel() {
    __shared__ float As[2][128 * LDA];
    __shared__ float Xs[2][128 * LDA];
    __shared__ float red[8];

    int tid = threadIdx.x;
    int warp = tid >> 5, lane = tid & 31;
    int wm = warp >> 2, wn = warp & 3;          // 2 x 4 warp grid
    int g = lane >> 2, c = lane & 3;
    int bid = blockIdx.x;
    int j0 = (bid & 15) * 128;   // m tile
    int i0 = (bid >> 4) * 128;   // n tile

    int lrow = tid & 127;        // loader row
    int lh = tid >> 7;           // loader k-half (0 or 1)

    int it = 0;
    for (; it < MAXIT; it++) {
        const float* __restrict__ Xin = (it & 1) ? g_X1buf : g_X0buf;
        float* __restrict__ Xout = (it & 1) ? g_X0buf : g_X1buf;

        float acc[4][4][4];
#pragma unroll
        for (int mi = 0; mi < 4; mi++)
#pragma unroll
            for (int ni = 0; ni < 4; ni++)
#pragma unroll
                for (int r = 0; r < 4; r++) acc[mi][ni][r] = 0.f;

        // stage 0 fill
        {
            const float* ap = g_Aproj + (size_t)(i0 + lrow) * N_DIM + lh * 8;
            const float* xp = Xin + (size_t)(j0 + lrow) * N_DIM + lh * 8;
            float4 a0 = *(const float4*)ap, a1 = *(const float4*)(ap + 4);
            float4 x0 = *(const float4*)xp, x1 = *(const float4*)(xp + 4);
            *(float4*)&As[0][lrow * LDA + lh * 8]     = a0;
            *(float4*)&As[0][lrow * LDA + lh * 8 + 4] = a1;
            *(float4*)&Xs[0][lrow * LDA + lh * 8]     = x0;
            *(float4*)&Xs[0][lrow * LDA + lh * 8 + 4] = x1;
        }
        __syncthreads();

        const int NST = N_DIM / KC;  // 64
        for (int s = 0; s < NST; s++) {
            int buf = s & 1;
            float4 a0, a1, x0, x1;
            if (s + 1 < NST) {
                int kk = KC * (s + 1);
                const float* ap = g_Aproj + (size_t)(i0 + lrow) * N_DIM + kk + lh * 8;
                const float* xp = Xin + (size_t)(j0 + lrow) * N_DIM + kk + lh * 8;
                a0 = *(const float4*)ap; a1 = *(const float4*)(ap + 4);
                x0 = *(const float4*)xp; x1 = *(const float4*)(xp + 4);
            }
#pragma unroll
            for (int k8 = 0; k8 < KC; k8 += 8) {
                uint32_t ah[4][4], al[4][4], bh[4][2], bl[4][2];
#pragma unroll
                for (int mi = 0; mi < 4; mi++) {
                    int r0 = wm * 64 + mi * 16 + g;
                    float o0 = As[buf][r0 * LDA + k8 + c];
                    float o1 = As[buf][(r0 + 8) * LDA + k8 + c];
                    float o2 = As[buf][r0 * LDA + k8 + c + 4];
                    float o3 = As[buf][(r0 + 8) * LDA + k8 + c + 4];
                    ah[mi][0] = f2tf(o0); al[mi][0] = f2tf(o0 - __uint_as_float(ah[mi][0]));
                    ah[mi][1] = f2tf(o1); al[mi][1] = f2tf(o1 - __uint_as_float(ah[mi][1]));
                    ah[mi][2] = f2tf(o2); al[mi][2] = f2tf(o2 - __uint_as_float(ah[mi][2]));
                    ah[mi][3] = f2tf(o3); al[mi][3] = f2tf(o3 - __uint_as_float(ah[mi][3]));
                }
#pragma unroll
                for (int ni = 0; ni < 4; ni++) {
                    int n0 = wn * 32 + ni * 8 + g;
                    float o0 = Xs[buf][n0 * LDA + k8 + c];
                    float o1 = Xs[buf][n0 * LDA + k8 + c + 4];
                    bh[ni][0] = f2tf(o0); bl[ni][0] = f2tf(o0 - __uint_as_float(bh[ni][0]));
                    bh[ni][1] = f2tf(o1); bl[ni][1] = f2tf(o1 - __uint_as_float(bh[ni][1]));
                }
#pragma unroll
                for (int mi = 0; mi < 4; mi++)
#pragma unroll
                    for (int ni = 0; ni < 4; ni++) {
                        mma8(acc[mi][ni], ah[mi], bh[ni]);
                        mma8(acc[mi][ni], ah[mi], bl[ni]);
                        mma8(acc[mi][ni], al[mi], bh[ni]);
                    }
            }
            if (s + 1 < NST) {
                int nb = buf ^ 1;
                *(float4*)&As[nb][lrow * LDA + lh * 8]     = a0;
                *(float4*)&As[nb][lrow * LDA + lh * 8 + 4] = a1;
                *(float4*)&Xs[nb][lrow * LDA + lh * 8]     = x0;
                *(float4*)&Xs[nb][lrow * LDA + lh * 8 + 4] = x1;
            }
            __syncthreads();
        }

        // epilogue: add BU, relu, diff, store (m-major)
        float maxd = 0.f;
#pragma unroll
        for (int mi = 0; mi < 4; mi++) {
#pragma unroll
            for (int ni = 0; ni < 4; ni++) {
#pragma unroll
                for (int r = 0; r < 4; r++) {
                    int il = wm * 64 + mi * 16 + g + ((r >= 2) ? 8 : 0);
                    int jl = wn * 32 + ni * 8 + 2 * c + (r & 1);
                    size_t adr = (size_t)(j0 + jl) * N_DIM + (i0 + il);
                    float v = fmaxf(acc[mi][ni][r] + g_BU[adr], 0.f);
                    maxd = fmaxf(maxd, fabsf(v - Xin[adr]));
                    Xout[adr] = v;
                }
            }
        }
#pragma unroll
        for (int o = 16; o; o >>= 1) maxd = fmaxf(maxd, __shfl_xor_sync(0xffffffffu, maxd, o));
        if (lane == 0) red[warp] = maxd;
        __syncthreads();
        if (tid == 0) {
            float m = red[0];
#pragma unroll
            for (int i2 = 1; i2 < 8; i2++) m = fmaxf(m, red[i2]);
            atomicMax(&g_md[it], __float_as_uint(m));
        }
        __syncthreads();

        // software grid barrier (128 blocks co-resident on 148 SMs)
        if (tid == 0) {
            __threadfence();
            atomicAdd(&g_barcnt, 1u);
            unsigned target = (unsigned)(it + 1) * NBLK;
            while (atomicAdd(&g_barcnt, 0u) < target) {}
            __threadfence();
        }
        __syncthreads();

        float md = __uint_as_float(g_md[it]);
        if (md <= TOL) { it++; break; }
    }

    if (bid == 0 && tid == 0) g_cur = it & 1;
}

// ---------------- final: k-split x4 partials ----------------
__global__ __launch_bounds__(256) void final_part_kernel(const float* __restrict__ Cm,
                                                         const float* __restrict__ Dm,
                                                         const float* __restrict__ U) {
    const float* __restrict__ Xm = g_cur ? g_X1buf : g_X0buf;
    __shared__ float As[16][132];
    __shared__ float Bs[16][132];
    int j0 = blockIdx.x * 128;
    int part = blockIdx.y;
    int tid = threadIdx.x;
    int lk = tid & 15, lb = tid >> 4;
    int tx = tid & 15, ty = tid >> 4;
    float acc[8][8] = {};

    int n_lo = part * (N_DIM / 4), n_hi = n_lo + N_DIM / 4;
    for (int kk = n_lo; kk < n_hi; kk += 16) {
        __syncthreads();
#pragma unroll
        for (int r = 0; r < 8; r++) {
            As[lk][lb + 16 * r] = Cm[(size_t)(lb + 16 * r) * N_DIM + kk + lk];
            Bs[lk][lb + 16 * r] = Xm[(size_t)(j0 + lb + 16 * r) * N_DIM + kk + lk];
        }
        __syncthreads();
#pragma unroll
        for (int k = 0; k < 16; k++) {
            float a[8], b[8];
#pragma unroll
            for (int i = 0; i < 8; i++) a[i] = As[k][ty * 8 + i];
#pragma unroll
            for (int j = 0; j < 8; j++) b[j] = Bs[k][tx * 8 + j];
#pragma unroll
            for (int i = 0; i < 8; i++)
#pragma unroll
                for (int j = 0; j < 8; j++) acc[i][j] = fmaf(a[i], b[j], acc[i][j]);
        }
    }
    int p_lo = part * (P_DIM / 4), p_hi = p_lo + P_DIM / 4;
    for (int kk = p_lo; kk < p_hi; kk += 16) {
        __syncthreads();
#pragma unroll
        for (int r = 0; r < 8; r++) {
            As[lk][lb + 16 * r] = Dm[(size_t)(lb + 16 * r) * P_DIM + kk + lk];
            Bs[lk][lb + 16 * r] = U[(size_t)(j0 + lb + 16 * r) * P_DIM + kk + lk];
        }
        __syncthreads();
#pragma unroll
        for (int k = 0; k < 16; k++) {
            float a[8], b[8];
#pragma unroll
            for (int i = 0; i < 8; i++) a[i] = As[k][ty * 8 + i];
#pragma unroll
            for (int j = 0; j < 8; j++) b[j] = Bs[k][tx * 8 + j];
#pragma unroll
            for (int i = 0; i < 8; i++)
#pragma unroll
                for (int j = 0; j < 8; j++) acc[i][j] = fmaf(a[i], b[j], acc[i][j]);
        }
    }
    float* outp = g_part[part];
#pragma unroll
    for (int j = 0; j < 8; j++) {
        size_t off = (size_t)(j0 + tx * 8 + j) * Q_DIM + ty * 8;
        *(float4*)(outp + off)     = make_float4(acc[0][j], acc[1][j], acc[2][j], acc[3][j]);
        *(float4*)(outp + off + 4) = make_float4(acc[4][j], acc[5][j], acc[6][j], acc[7][j]);
    }
}

__global__ void final_reduce_kernel(float* __restrict__ outp) {
    size_t idx = (size_t)blockIdx.x * 256 + threadIdx.x;
    size_t tot = (size_t)M_DIM * Q_DIM / 4;
    const float4* p0 = (const float4*)g_part[0];
    const float4* p1 = (const float4*)g_part[1];
    const float4* p2 = (const float4*)g_part[2];
    const float4* p3 = (const float4*)g_part[3];
    float4* o = (float4*)outp;
    for (size_t i = idx; i < tot; i += (size_t)gridDim.x * 256) {
        float4 a = p0[i], b = p1[i], c = p2[i], d = p3[i];
        o[i] = make_float4(a.x + b.x + c.x + d.x, a.y + b.y + c.y + d.y,
                           a.z + b.z + c.z + d.z, a.w + b.w + c.w + d.w);
    }
}

// ---------------- launcher ----------------
extern "C" void kernel_launch(void* const* d_in, const int* in_sizes, int n_in,
                              void* d_out, int out_size) {
    (void)in_sizes; (void)n_in; (void)out_size;
    const float* U  = (const float*)d_in[0];
    const float* X0 = (const float*)d_in[1];
    const float* A  = (const float*)d_in[2];
    const float* B  = (const float*)d_in[3];
    const float* Cm = (const float*)d_in[4];
    const float* Dm = (const float*)d_in[5];
    float* outp = (float*)d_out;

    init_kernel<<<1, 256>>>();
    project_kernel<<<N_DIM, 256>>>(A);
    copyx0_kernel<<<512, 256>>>(X0);
    bu_kernel<<<dim3(M_DIM / 128, N_DIM / 64), 256>>>(B, U);
    picard_kernel<<<NBLK, 256>>>();
    final_part_kernel<<<dim3(M_DIM / 128, 4), 256>>>(Cm, Dm, U);
    final_reduce_kernel<<<64, 256>>>(outp);
}

// round 6
// speedup vs baseline: 2.3903x; 1.2801x over previous
#include <cuda_runtime.h>
#include <cstdint>

#define N_DIM 1024
#define M_DIM 2048
#define P_DIM 512
#define Q_DIM 128
#define KAPPA 0.99f
#define TOL   3e-6f
#define SWITCH_MD 1e-3f
#define MAXIT 300
#define NBLK  128

#define KC   16
#define LDA  20                 // padded smem row (floats); stride-20 bank walk conflict-free
#define SMSZ 2560               // 128*LDA floats per buffer
#define DSMEM_BYTES (8 * SMSZ * 4)   // Ah,Al,Xh,Xl x double buffer = 81920 B

// ---------------- device state ----------------
__device__ float g_Aproj[(size_t)N_DIM * N_DIM];
__device__ float g_BU[(size_t)M_DIM * N_DIM];     // m-major
__device__ float g_Y0[(size_t)M_DIM * N_DIM];     // m-major, pre-relu refresh output
__device__ float g_X0buf[(size_t)M_DIM * N_DIM];  // m-major X ping-pong
__device__ float g_X1buf[(size_t)M_DIM * N_DIM];
__device__ float g_dX0[(size_t)M_DIM * N_DIM];    // residual ping-pong
__device__ float g_dX1[(size_t)M_DIM * N_DIM];
__device__ float g_part[8][(size_t)M_DIM * Q_DIM];
__device__ unsigned g_md[MAXIT];
__device__ unsigned g_barcnt;
__device__ float* g_fp1;
__device__ float* g_fp2;
__device__ int g_resid;

// ---------------- helpers ----------------
__device__ __forceinline__ uint32_t f2tf(float x) {
    uint32_t r;
    asm("cvt.rna.tf32.f32 %0, %1;" : "=r"(r) : "f"(x));
    return r;
}
__device__ __forceinline__ void mma8(float* d, const uint32_t* a, const uint32_t* b) {
    asm volatile(
        "mma.sync.aligned.m16n8k8.row.col.f32.tf32.tf32.f32 "
        "{%0,%1,%2,%3},{%4,%5,%6,%7},{%8,%9},{%0,%1,%2,%3};"
        : "+f"(d[0]), "+f"(d[1]), "+f"(d[2]), "+f"(d[3])
        : "r"(a[0]), "r"(a[1]), "r"(a[2]), "r"(a[3]), "r"(b[0]), "r"(b[1]));
}
__device__ __forceinline__ void split_st(float* hi, float* lo, int off, float4 v, int full) {
    float4 h;
    h.x = __uint_as_float(f2tf(v.x)); h.y = __uint_as_float(f2tf(v.y));
    h.z = __uint_as_float(f2tf(v.z)); h.w = __uint_as_float(f2tf(v.w));
    *(float4*)&hi[off] = h;
    if (full) {
        float4 l;
        l.x = __uint_as_float(f2tf(v.x - h.x)); l.y = __uint_as_float(f2tf(v.y - h.y));
        l.z = __uint_as_float(f2tf(v.z - h.z)); l.w = __uint_as_float(f2tf(v.w - h.w));
        *(float4*)&lo[off] = l;
    }
}

// ---------------- shared 128x128 GEMM tile: acc += Ab(128,k) * Bb(128,k)^T ----------------
__device__ __forceinline__ void gemm_tile(
    const float* __restrict__ Ab, int lda,
    const float* __restrict__ Bb, int ldb,
    int kdim, int full, float* __restrict__ sm, float acc[4][4][4])
{
    float* Ah = sm;
    float* Al = sm + 2 * SMSZ;
    float* Xh = sm + 4 * SMSZ;
    float* Xl = sm + 6 * SMSZ;
    int tid = threadIdx.x;
    int warp = tid >> 5, lane = tid & 31;
    int wm = warp >> 2, wn = warp & 3;
    int g = lane >> 2, c = lane & 3;
    int lrow = tid & 127, lh = tid >> 7;
    int sbase = lrow * LDA + lh * 8;

#pragma unroll
    for (int mi = 0; mi < 4; mi++)
#pragma unroll
        for (int ni = 0; ni < 4; ni++)
#pragma unroll
            for (int r = 0; r < 4; r++) acc[mi][ni][r] = 0.f;

    const float* ap = Ab + (size_t)lrow * lda;
    const float* xp = Bb + (size_t)lrow * ldb;
    float4 a0 = *(const float4*)(ap + lh * 8);
    float4 a1 = *(const float4*)(ap + lh * 8 + 4);
    float4 x0 = *(const float4*)(xp + lh * 8);
    float4 x1 = *(const float4*)(xp + lh * 8 + 4);
    split_st(Ah, Al, sbase, a0, full);
    split_st(Ah, Al, sbase + 4, a1, full);
    split_st(Xh, Xl, sbase, x0, full);
    split_st(Xh, Xl, sbase + 4, x1, full);
    __syncthreads();

    int NST = kdim / KC;
    for (int s = 0; s < NST; s++) {
        int buf = s & 1;
        int ab = buf * SMSZ;
        if (s + 1 < NST) {
            int kk = KC * (s + 1);
            a0 = *(const float4*)(ap + kk + lh * 8);
            a1 = *(const float4*)(ap + kk + lh * 8 + 4);
            x0 = *(const float4*)(xp + kk + lh * 8);
            x1 = *(const float4*)(xp + kk + lh * 8 + 4);
        }
#pragma unroll
        for (int k8 = 0; k8 < KC; k8 += 8) {
            uint32_t ahf[4][4], bhf[4][2];
#pragma unroll
            for (int mi = 0; mi < 4; mi++) {
                int r0 = wm * 64 + mi * 16 + g;
                const float* p = &Ah[ab + r0 * LDA + k8 + c];
                ahf[mi][0] = __float_as_uint(p[0]);
                ahf[mi][1] = __float_as_uint(p[8 * LDA]);
                ahf[mi][2] = __float_as_uint(p[4]);
                ahf[mi][3] = __float_as_uint(p[8 * LDA + 4]);
            }
#pragma unroll
            for (int ni = 0; ni < 4; ni++) {
                int n0 = wn * 32 + ni * 8 + g;
                const float* p = &Xh[ab + n0 * LDA + k8 + c];
                bhf[ni][0] = __float_as_uint(p[0]);
                bhf[ni][1] = __float_as_uint(p[4]);
            }
            if (full) {
                uint32_t alf[4][4], blf[4][2];
#pragma unroll
                for (int mi = 0; mi < 4; mi++) {
                    int r0 = wm * 64 + mi * 16 + g;
                    const float* p = &Al[ab + r0 * LDA + k8 + c];
                    alf[mi][0] = __float_as_uint(p[0]);
                    alf[mi][1] = __float_as_uint(p[8 * LDA]);
                    alf[mi][2] = __float_as_uint(p[4]);
                    alf[mi][3] = __float_as_uint(p[8 * LDA + 4]);
                }
#pragma unroll
                for (int ni = 0; ni < 4; ni++) {
                    int n0 = wn * 32 + ni * 8 + g;
                    const float* p = &Xl[ab + n0 * LDA + k8 + c];
                    blf[ni][0] = __float_as_uint(p[0]);
                    blf[ni][1] = __float_as_uint(p[4]);
                }
#pragma unroll
                for (int mi = 0; mi < 4; mi++)
#pragma unroll
                    for (int ni = 0; ni < 4; ni++) {
                        mma8(acc[mi][ni], ahf[mi], bhf[ni]);
                        mma8(acc[mi][ni], ahf[mi], blf[ni]);
                        mma8(acc[mi][ni], alf[mi], bhf[ni]);
                    }
            } else {
#pragma unroll
                for (int mi = 0; mi < 4; mi++)
#pragma unroll
                    for (int ni = 0; ni < 4; ni++)
                        mma8(acc[mi][ni], ahf[mi], bhf[ni]);
            }
        }
        if (s + 1 < NST) {
            int nb = (buf ^ 1) * SMSZ + sbase;
            split_st(Ah, Al, nb, a0, full);
            split_st(Ah, Al, nb + 4, a1, full);
            split_st(Xh, Xl, nb, x0, full);
            split_st(Xh, Xl, nb + 4, x1, full);
        }
        __syncthreads();
    }
}

// ---------------- init ----------------
__global__ void init_kernel() {
    int t = threadIdx.x;
    for (int i = t; i < MAXIT; i += 256) g_md[i] = 0u;
    if (t == 0) { g_barcnt = 0u; g_resid = 0; }
}

// ---------------- row-wise L-inf projection of A ----------------
__global__ __launch_bounds__(256) void project_kernel(const float* __restrict__ A) {
    __shared__ float warp_s[8];
    __shared__ float s_scale;
    int row = blockIdx.x;
    const float* ar = A + (size_t)row * N_DIM;
    float s = 0.f;
    for (int c = threadIdx.x; c < N_DIM; c += 256) s += fabsf(ar[c]);
#pragma unroll
    for (int o = 16; o; o >>= 1) s += __shfl_xor_sync(0xffffffffu, s, o);
    if ((threadIdx.x & 31) == 0) warp_s[threadIdx.x >> 5] = s;
    __syncthreads();
    if (threadIdx.x == 0) {
        float t = 0.f;
#pragma unroll
        for (int i = 0; i < 8; i++) t += warp_s[i];
        s_scale = fminf(1.f, KAPPA / fmaxf(t, 1e-12f));
    }
    __syncthreads();
    float sc = s_scale;
    float* outp = g_Aproj + (size_t)row * N_DIM;
    for (int c = threadIdx.x; c < N_DIM; c += 256) outp[c] = ar[c] * sc;
}

// ---------------- X0 (m,n) row-major == m-major: straight copy ----------------
__global__ void copyx0_kernel(const float* __restrict__ in) {
    size_t idx = (size_t)blockIdx.x * 256 + threadIdx.x;
    const float4* src = (const float4*)in;
    float4* dst = (float4*)g_X0buf;
    size_t tot = (size_t)M_DIM * N_DIM / 4;
    for (size_t i = idx; i < tot; i += (size_t)gridDim.x * 256) dst[i] = src[i];
}

// ---------------- BU[j][i] = sum_p B[i,p] U[j,p] via 3xTF32 tensor tile ----------------
__global__ __launch_bounds__(256) void bu_kernel_t(const float* __restrict__ B,
                                                   const float* __restrict__ U) {
    extern __shared__ float sm[];
    int bid = blockIdx.x;
    int j0 = (bid & 15) * 128;
    int i0 = (bid >> 4) * 128;
    float acc[4][4][4];
    gemm_tile(B + (size_t)i0 * P_DIM, P_DIM, U + (size_t)j0 * P_DIM, P_DIM,
              P_DIM, 1, sm, acc);

    int warp = threadIdx.x >> 5, lane = threadIdx.x & 31;
    int wm = warp >> 2, wn = warp & 3;
    int g = lane >> 2, c = lane & 3;
#pragma unroll
    for (int mi = 0; mi < 4; mi++)
#pragma unroll
        for (int ni = 0; ni < 4; ni++)
#pragma unroll
            for (int r = 0; r < 4; r++) {
                int il = wm * 64 + mi * 16 + g + ((r >= 2) ? 8 : 0);
                int jl = wn * 32 + ni * 8 + 2 * c + (r & 1);
                g_BU[(size_t)(j0 + jl) * N_DIM + (i0 + il)] = acc[mi][ni][r];
            }
}

// ---------------- persistent hybrid Picard loop ----------------
__global__ __launch_bounds__(256, 1) void picard_kernel() {
    extern __shared__ float sm[];
    __shared__ float red[8];

    int tid = threadIdx.x;
    int warp = tid >> 5, lane = tid & 31;
    int wm = warp >> 2, wn = warp & 3;
    int g = lane >> 2, c = lane & 3;
    int bid = blockIdx.x;
    int j0 = (bid & 15) * 128;   // m tile
    int i0 = (bid >> 4) * 128;   // n tile

    float* Xb[2] = {g_X0buf, g_X1buf};
    float* Dd[2] = {g_dX0, g_dX1};

    int phase = 0;      // 0 = fast X, 1 = refresh, 2 = residual
    int curX = 0, curD = 0, base = 0;
    float* fin1 = g_X0buf;
    float* fin2 = g_X0buf;
    int finR = 0;

    for (int it = 0; it < MAXIT; it++) {
        int mode = phase;
        const float* __restrict__ in = (mode == 2) ? Dd[curD] : Xb[curX];
        float* __restrict__ out = (mode == 0) ? Xb[curX ^ 1]
                                 : (mode == 1) ? Dd[0] : Dd[curD ^ 1];
        int full = (mode == 1);
        const float* __restrict__ Xbase = Xb[(mode == 1) ? curX : base];

        float acc[4][4][4];
        gemm_tile(g_Aproj + (size_t)i0 * N_DIM, N_DIM, in + (size_t)j0 * N_DIM, N_DIM,
                  N_DIM, full, sm, acc);

        // epilogue
        float maxd = 0.f;
#pragma unroll
        for (int mi = 0; mi < 4; mi++)
#pragma unroll
            for (int ni = 0; ni < 4; ni++)
#pragma unroll
                for (int r = 0; r < 4; r++) {
                    int il = wm * 64 + mi * 16 + g + ((r >= 2) ? 8 : 0);
                    int jl = wn * 32 + ni * 8 + 2 * c + (r & 1);
                    size_t adr = (size_t)(j0 + jl) * N_DIM + (i0 + il);
                    float a = acc[mi][ni][r];
                    if (mode == 0) {
                        float v = fmaxf(a + g_BU[adr], 0.f);
                        maxd = fmaxf(maxd, fabsf(v - in[adr]));
                        out[adr] = v;
                    } else if (mode == 1) {
                        float t = a + g_BU[adr];
                        g_Y0[adr] = t;
                        float v = fmaxf(t, 0.f);
                        float d = v - in[adr];      // Xbase == in
                        maxd = fmaxf(maxd, fabsf(d));
                        out[adr] = d;
                    } else {
                        float v = fmaxf(a + g_Y0[adr], 0.f);
                        float d = v - Xbase[adr];
                        maxd = fmaxf(maxd, fabsf(d - in[adr]));
                        out[adr] = d;
                    }
                }
#pragma unroll
        for (int o = 16; o; o >>= 1) maxd = fmaxf(maxd, __shfl_xor_sync(0xffffffffu, maxd, o));
        if (lane == 0) red[warp] = maxd;
        __syncthreads();
        if (tid == 0) {
            float m = red[0];
#pragma unroll
            for (int i2 = 1; i2 < 8; i2++) m = fmaxf(m, red[i2]);
            atomicMax(&g_md[it], __float_as_uint(m));
        }
        __syncthreads();

        // software grid barrier (128 blocks co-resident on 148 SMs)
        if (tid == 0) {
            __threadfence();
            atomicAdd(&g_barcnt, 1u);
            unsigned target = (unsigned)(it + 1) * NBLK;
            while (atomicAdd(&g_barcnt, 0u) < target) {}
            __threadfence();
        }
        __syncthreads();

        float md = __uint_as_float(g_md[it]);
        fin1 = (mode == 0) ? out : (float*)Xbase;
        fin2 = out;
        finR = (mode >= 1);
        if (md <= TOL) break;

        if (mode == 0) {
            curX ^= 1;
            if (md <= SWITCH_MD) phase = 1;
        } else if (mode == 1) {
            base = curX;
            phase = 2;
            curD = 0;
        } else {
            curD ^= 1;
        }
    }

    if (bid == 0 && tid == 0) {
        g_fp1 = fin1;
        g_fp2 = fin2;
        g_resid = finR;
    }
}

// ---------------- final: k-split x8 partials; X = fp1 (+ fp2 if resid) ----------------
__global__ __launch_bounds__(256) void final_part_kernel(const float* __restrict__ Cm,
                                                         const float* __restrict__ Dm,
                                                         const float* __restrict__ U) {
    const float* __restrict__ F1 = g_fp1;
    const float* __restrict__ F2 = g_fp2;
    int resid = g_resid;
    __shared__ float As[16][132];
    __shared__ float Bs[16][132];
    int j0 = blockIdx.x * 128;
    int part = blockIdx.y;      // 0..7
    int tid = threadIdx.x;
    int lk = tid & 15, lb = tid >> 4;
    int tx = tid & 15, ty = tid >> 4;
    float acc[8][8] = {};

    int n_lo = part * (N_DIM / 8), n_hi = n_lo + N_DIM / 8;
    for (int kk = n_lo; kk < n_hi; kk += 16) {
        __syncthreads();
#pragma unroll
        for (int r = 0; r < 8; r++) {
            As[lk][lb + 16 * r] = Cm[(size_t)(lb + 16 * r) * N_DIM + kk + lk];
            size_t off = (size_t)(j0 + lb + 16 * r) * N_DIM + kk + lk;
            float xv = F1[off];
            if (resid) xv += F2[off];
            Bs[lk][lb + 16 * r] = xv;
        }
        __syncthreads();
#pragma unroll
        for (int k = 0; k < 16; k++) {
            float a[8], b[8];
#pragma unroll
            for (int i = 0; i < 8; i++) a[i] = As[k][ty * 8 + i];
#pragma unroll
            for (int j = 0; j < 8; j++) b[j] = Bs[k][tx * 8 + j];
#pragma unroll
            for (int i = 0; i < 8; i++)
#pragma unroll
                for (int j = 0; j < 8; j++) acc[i][j] = fmaf(a[i], b[j], acc[i][j]);
        }
    }
    int p_lo = part * (P_DIM / 8), p_hi = p_lo + P_DIM / 8;
    for (int kk = p_lo; kk < p_hi; kk += 16) {
        __syncthreads();
#pragma unroll
        for (int r = 0; r < 8; r++) {
            As[lk][lb + 16 * r] = Dm[(size_t)(lb + 16 * r) * P_DIM + kk + lk];
            Bs[lk][lb + 16 * r] = U[(size_t)(j0 + lb + 16 * r) * P_DIM + kk + lk];
        }
        __syncthreads();
#pragma unroll
        for (int k = 0; k < 16; k++) {
            float a[8], b[8];
#pragma unroll
            for (int i = 0; i < 8; i++) a[i] = As[k][ty * 8 + i];
#pragma unroll
            for (int j = 0; j < 8; j++) b[j] = Bs[k][tx * 8 + j];
#pragma unroll
            for (int i = 0; i < 8; i++)
#pragma unroll
                for (int j = 0; j < 8; j++) acc[i][j] = fmaf(a[i], b[j], acc[i][j]);
        }
    }
    float* outp = g_part[part];
#pragma unroll
    for (int j = 0; j < 8; j++) {
        size_t off = (size_t)(j0 + tx * 8 + j) * Q_DIM + ty * 8;
        *(float4*)(outp + off)     = make_float4(acc[0][j], acc[1][j], acc[2][j], acc[3][j]);
        *(float4*)(outp + off + 4) = make_float4(acc[4][j], acc[5][j], acc[6][j], acc[7][j]);
    }
}

__global__ void final_reduce_kernel(float* __restrict__ outp) {
    size_t idx = (size_t)blockIdx.x * 256 + threadIdx.x;
    size_t tot = (size_t)M_DIM * Q_DIM / 4;
    float4* o = (float4*)outp;
    for (size_t i = idx; i < tot; i += (size_t)gridDim.x * 256) {
        float4 s = ((const float4*)g_part[0])[i];
#pragma unroll
        for (int p = 1; p < 8; p++) {
            float4 v = ((const float4*)g_part[p])[i];
            s.x += v.x; s.y += v.y; s.z += v.z; s.w += v.w;
        }
        o[i] = s;
    }
}

// ---------------- launcher ----------------
extern "C" void kernel_launch(void* const* d_in, const int* in_sizes, int n_in,
                              void* d_out, int out_size) {
    (void)in_sizes; (void)n_in; (void)out_size;
    const float* U  = (const float*)d_in[0];
    const float* X0 = (const float*)d_in[1];
    const float* A  = (const float*)d_in[2];
    const float* B  = (const float*)d_in[3];
    const float* Cm = (const float*)d_in[4];
    const float* Dm = (const float*)d_in[5];
    float* outp = (float*)d_out;

    cudaFuncSetAttribute(picard_kernel, cudaFuncAttributeMaxDynamicSharedMemorySize, DSMEM_BYTES);
    cudaFuncSetAttribute(bu_kernel_t, cudaFuncAttributeMaxDynamicSharedMemorySize, DSMEM_BYTES);

    init_kernel<<<1, 256>>>();
    project_kernel<<<N_DIM, 256>>>(A);
    copyx0_kernel<<<512, 256>>>(X0);
    bu_kernel_t<<<NBLK, 256, DSMEM_BYTES>>>(B, U);
    picard_kernel<<<NBLK, 256, DSMEM_BYTES>>>();
    final_part_kernel<<<dim3(M_DIM / 128, 8), 256>>>(Cm, Dm, U);
    final_reduce_kernel<<<64, 256>>>(outp);
}